// round 15
// baseline (speedup 1.0000x reference)
#include <cuda_runtime.h>

#define NN 100000
#define EE 1000000
#define GG 1024
#define FDIM 44
#define PAD 64           // padded node-feature row stride (floats) = 256B
#define FEATD 1019
#define GCOLS 22
#define GCP   24   // padded sW row (6 x ulonglong2)

// ---------------- static scratch ----------------
__device__ int      g_cnt[NN];
__device__ int      g_off[NN];
__device__ int      g_cur[NN];
__device__ int      g_alloc;
__device__ float    g_dinv[NN];
__device__ __align__(16) float2 g_csr[EE + NN];  // {src*PAD (int bits), norm}; rows even-aligned
__device__ __align__(256) float g_bufA[(size_t)NN * PAD];
__device__ __align__(16)  float g_bufB[(size_t)NN * 96];
__device__ __align__(256) float g_t1[(size_t)NN * PAD];
__device__ __align__(256) float g_t2[(size_t)NN * PAD];
__device__ unsigned g_pool[GG * FDIM];

// ---------------- histogram ----------------
__global__ void hist_k(const int* __restrict__ dst) {
    int e = blockIdx.x * blockDim.x + threadIdx.x;
    if (e < EE) atomicAdd(&g_cnt[dst[e]], 1);
}

// ---------------- bump allocation of CSR rows (even-aligned starts) ----------
__global__ void alloc_k() {
    int i = blockIdx.x * blockDim.x + threadIdx.x;
    int lane = threadIdx.x & 31;
    int c = (i < NN) ? g_cnt[i] : 0;
    int cp = (c + 1) & ~1;
    int s = cp;
#pragma unroll
    for (int o = 1; o < 32; o <<= 1) {
        int t = __shfl_up_sync(0xffffffffu, s, o);
        if (lane >= o) s += t;
    }
    int base = 0;
    if (lane == 31) base = atomicAdd(&g_alloc, s);
    base = __shfl_sync(0xffffffffu, base, 31);
    int off = base + s - cp;
    if (i < NN) {
        g_off[i] = off;
        g_cur[i] = off;
        g_dinv[i] = rsqrtf((float)c + 1.0f);
    }
}

// ---------------- edge binning (store pre-scaled float offset src*PAD) -------
__global__ void bin_k(const int* __restrict__ src, const int* __restrict__ dst) {
    int e = blockIdx.x * blockDim.x + threadIdx.x;
    if (e >= EE) return;
    int s = __ldg(&src[e]);
    int d = __ldg(&dst[e]);
    int pos = atomicAdd(&g_cur[d], 1);
    g_csr[pos] = make_float2(__int_as_float(s << 6), g_dinv[s] * g_dinv[d]);  // s*PAD
}

// ---------------- warp-per-node aggregation on 256B-aligned rows -------------
// MODE 0: plain   MODE 1: relu(agg + b)   MODE 2: pool(relu(agg + b))
template <int MODE>
__global__ __launch_bounds__(128) void agg44_k(const float* __restrict__ in,
                                               const float* __restrict__ b,
                                               float* __restrict__ out,
                                               const int* __restrict__ batch) {
    int node = blockIdx.x * 4 + (threadIdx.x >> 5);
    if (node >= NN) return;
    const int lane = threadIdx.x & 31;
    const bool hi = lane < (FDIM - 32);   // 12 lanes own chunk 1

    const float* __restrict__ base0 = in + lane;
    const int selfoff = node * PAD;

    float di = g_dinv[node];
    float sc = di * di;
    float acc0 = __ldg(&base0[selfoff]) * sc;
    float acc1 = hi ? __ldg(&base0[selfoff + 32]) * sc : 0.0f;

    const int n = g_cnt[node];
    const float2* __restrict__ csr = g_csr + g_off[node];   // even-aligned

    int j = 0;
    for (; j + 4 <= n; j += 4) {
        const float4* c4 = reinterpret_cast<const float4*>(csr + j);
        float4 p0 = __ldg(&c4[0]);
        float4 p1 = __ldg(&c4[1]);
        int o0 = __float_as_int(p0.x), o1 = __float_as_int(p0.z);
        int o2 = __float_as_int(p1.x), o3 = __float_as_int(p1.z);
        float v00 = __ldg(&base0[o0]);
        float v10 = __ldg(&base0[o1]);
        float v20 = __ldg(&base0[o2]);
        float v30 = __ldg(&base0[o3]);
        float v01 = hi ? __ldg(&base0[o0 + 32]) : 0.0f;
        float v11 = hi ? __ldg(&base0[o1 + 32]) : 0.0f;
        float v21 = hi ? __ldg(&base0[o2 + 32]) : 0.0f;
        float v31 = hi ? __ldg(&base0[o3 + 32]) : 0.0f;
        acc0 += v00 * p0.y + v10 * p0.w + v20 * p1.y + v30 * p1.w;
        acc1 += v01 * p0.y + v11 * p0.w + v21 * p1.y + v31 * p1.w;
    }
    for (; j < n; j++) {
        float2 c = __ldg(&csr[j]);
        int o = __float_as_int(c.x);
        acc0 += __ldg(&base0[o]) * c.y;
        if (hi) acc1 += __ldg(&base0[o + 32]) * c.y;
    }

    if (MODE == 2) {
        acc0 = fmaxf(acc0 + __ldg(&b[lane]), 0.0f);
        unsigned gbase = (unsigned)__ldg(&batch[node]) * FDIM;
        atomicMax(&g_pool[gbase + lane], __float_as_uint(acc0));
        if (hi) {
            acc1 = fmaxf(acc1 + __ldg(&b[32 + lane]), 0.0f);
            atomicMax(&g_pool[gbase + 32 + lane], __float_as_uint(acc1));
        }
    } else {
        if (MODE == 1) {
            acc0 = fmaxf(acc0 + __ldg(&b[lane]), 0.0f);
            if (hi) acc1 = fmaxf(acc1 + __ldg(&b[32 + lane]), 0.0f);
        }
        out[selfoff + lane] = acc0;
        if (hi) out[selfoff + 32 + lane] = acc1;
    }
}

// ---------------- GEMM v4: smem-staged, fully coalesced global I/O -----------
template <int FIN, int INS, int FOUT, int OUTS, bool RELU>
__global__ __launch_bounds__(256, 4) void gemm4_k(const float* __restrict__ in,
                                                  const float* __restrict__ W,
                                                  const float* __restrict__ b,
                                                  float* __restrict__ out) {
    constexpr int NPHASE = FIN / 44;
    __shared__ __align__(16) float sIn[256 * 44];   // 45KB; reused as output staging
    __shared__ __align__(16) float sW[FIN * GCP];
    __shared__ float sB[GCOLS];

    const int t = threadIdx.x;
    const int col0 = blockIdx.y * GCOLS;
    const int n0 = blockIdx.x * 256;
    const int nrows = (NN - n0 < 256) ? (NN - n0) : 256;

    for (int i = t; i < FIN * GCP; i += 256) {
        int k = i / GCP, c = i - k * GCP;
        sW[i] = (c < GCOLS) ? W[k * FOUT + col0 + c] : 0.0f;
    }
    if (t < GCOLS) sB[t] = b ? b[col0 + t] : 0.0f;

    unsigned long long acc[11];

    const float4* __restrict__ gin = reinterpret_cast<const float4*>(in);
#pragma unroll 1
    for (int p = 0; p < NPHASE; p++) {
        __syncthreads();
#pragma unroll
        for (int s = 0; s < 11; s++) {
            int i = t + 256 * s;
            int row = i / 11;
            int c = i - row * 11;
            float4 v = (row < nrows)
                ? __ldg(&gin[(size_t)(n0 + row) * (INS / 4) + p * 11 + c])
                : make_float4(0.f, 0.f, 0.f, 0.f);
            reinterpret_cast<float4*>(sIn)[i] = v;
        }
        __syncthreads();
        if (p == 0) {
#pragma unroll
            for (int c2 = 0; c2 < 11; c2++) {
                float lo = sB[2 * c2], hi = sB[2 * c2 + 1];
                asm("mov.b64 %0, {%1, %2};" : "=l"(acc[c2]) : "f"(lo), "f"(hi));
            }
        }
        const float4* __restrict__ s4 = reinterpret_cast<const float4*>(sIn) + t * 11;
#pragma unroll
        for (int k4 = 0; k4 < 11; k4++) {
            float4 a = s4[k4];
            float av[4] = {a.x, a.y, a.z, a.w};
#pragma unroll
            for (int kk = 0; kk < 4; kk++) {
                const int k = p * 44 + k4 * 4 + kk;
                unsigned long long ad;
                asm("mov.b64 %0, {%1, %1};" : "=l"(ad) : "f"(av[kk]));
                const ulonglong2* __restrict__ w2p =
                    reinterpret_cast<const ulonglong2*>(sW + k * GCP);
#pragma unroll
                for (int c2 = 0; c2 < 6; c2++) {
                    ulonglong2 wv = w2p[c2];
                    asm("fma.rn.f32x2 %0, %1, %2, %0;" : "+l"(acc[2 * c2 > 10 ? 10 : 2 * c2]) : "l"(ad), "l"(wv.x));
                    if (2 * c2 + 1 < 11) {
                        asm("fma.rn.f32x2 %0, %1, %2, %0;" : "+l"(acc[2 * c2 + 1]) : "l"(ad), "l"(wv.y));
                    }
                }
            }
        }
    }
    __syncthreads();

    unsigned long long* so = reinterpret_cast<unsigned long long*>(sIn);
#pragma unroll
    for (int c2 = 0; c2 < 11; c2++) {
        float lo, hi;
        asm("mov.b64 {%0, %1}, %2;" : "=f"(lo), "=f"(hi) : "l"(acc[c2]));
        if (RELU) { lo = fmaxf(lo, 0.0f); hi = fmaxf(hi, 0.0f); }
        unsigned long long v;
        asm("mov.b64 %0, {%1, %2};" : "=l"(v) : "f"(lo), "f"(hi));
        so[t * 11 + c2] = v;
    }
    __syncthreads();

    float2* __restrict__ gout = reinterpret_cast<float2*>(out);
#pragma unroll
    for (int s = 0; s < 11; s++) {
        int i = t + 256 * s;
        int row = i / 11;
        int c = i - row * 11;
        if (row < nrows)
            gout[(size_t)(n0 + row) * (OUTS / 2) + col0 / 2 + c] =
                reinterpret_cast<float2*>(sIn)[i];
    }
}

// ---------------- heads (split-K over 2 thread halves) ----------------
__global__ __launch_bounds__(256) void final_k(
        const float* __restrict__ feature,
        const float* __restrict__ Wg,  const float* __restrict__ bg,
        const float* __restrict__ Wf1, const float* __restrict__ bf1,
        const float* __restrict__ Wf2, const float* __restrict__ bf2,
        float* __restrict__ out) {
    constexpr int GPB = 8;
    constexpr int KSPLIT = 512;
    __shared__ float sf[GPB][1024];
    __shared__ float sacc[GPB][128];
    __shared__ float red1[GPB][4], red2[GPB][4];
    const int g0 = blockIdx.x * GPB;
    const int t = threadIdx.x;   // 256
    const int h = t & 127;
    const int half = t >> 7;

#pragma unroll
    for (int q = 0; q < GPB; q++)
        for (int k = t; k < FEATD; k += 256)
            sf[q][k] = feature[(size_t)(g0 + q) * FEATD + k];
    __syncthreads();

    float acc[GPB];
    const float bb = (half == 0) ? bf1[h] : 0.0f;
#pragma unroll
    for (int q = 0; q < GPB; q++) acc[q] = bb;
    const int k0 = half ? KSPLIT : 0;
    const int k1 = half ? FEATD : KSPLIT;
    for (int k = k0; k < k1; k++) {
        float w = __ldg(&Wf1[k * 128 + h]);
#pragma unroll
        for (int q = 0; q < GPB; q++) acc[q] += sf[q][k] * w;
    }
    if (half == 1) {
#pragma unroll
        for (int q = 0; q < GPB; q++) sacc[q][h] = acc[q];
    }
    __syncthreads();

    if (half == 0) {
        const float w2 = Wf2[h];
        const float wg = (h < FDIM) ? Wg[h] : 0.0f;
        const int lane = h & 31, wid = h >> 5;
#pragma unroll
        for (int q = 0; q < GPB; q++) {
            float hidden = acc[q] + sacc[q][h];
            float s2 = fmaxf(hidden, 0.0f) * w2;
            float s1 = (h < FDIM) ? __uint_as_float(g_pool[(g0 + q) * FDIM + h]) * wg : 0.0f;
#pragma unroll
            for (int o = 16; o; o >>= 1) {
                s1 += __shfl_down_sync(0xffffffffu, s1, o);
                s2 += __shfl_down_sync(0xffffffffu, s2, o);
            }
            if (lane == 0) { red1[q][wid] = s1; red2[q][wid] = s2; }
        }
    }
    __syncthreads();
    if (t < GPB) {
        int q = t;
        float a = red1[q][0] + red1[q][1] + red1[q][2] + red1[q][3];
        float c = red2[q][0] + red2[q][1] + red2[q][2] + red2[q][3];
        out[g0 + q] = fmaxf(a + bg[0], 0.0f) + c + bf2[0];
    }
}

// ---------------- launch ----------------
extern "C" void kernel_launch(void* const* d_in, const int* in_sizes, int n_in,
                              void* d_out, int out_size) {
    const float* x       = (const float*)d_in[0];
    const int*   ei      = (const int*)d_in[1];
    const int*   batch   = (const int*)d_in[2];
    const float* feature = (const float*)d_in[3];
    const float* W1 = (const float*)d_in[4];
    const float* b1 = (const float*)d_in[5];
    const float* W2 = (const float*)d_in[6];
    const float* b2 = (const float*)d_in[7];
    const float* W3 = (const float*)d_in[8];
    const float* b3 = (const float*)d_in[9];
    const float* Wg = (const float*)d_in[10];
    const float* bg = (const float*)d_in[11];
    const float* Wf1 = (const float*)d_in[12];
    const float* bf1 = (const float*)d_in[13];
    const float* Wf2 = (const float*)d_in[14];
    const float* bf2 = (const float*)d_in[15];
    float* out = (float*)d_out;

    const int* src = ei;        // edge_index[0]
    const int* dst = ei + EE;   // edge_index[1]

    void *pA, *pB, *pT1, *pT2, *pCnt, *pPool, *pAlloc;
    cudaGetSymbolAddress(&pA, g_bufA);
    cudaGetSymbolAddress(&pB, g_bufB);
    cudaGetSymbolAddress(&pT1, g_t1);
    cudaGetSymbolAddress(&pT2, g_t2);
    cudaGetSymbolAddress(&pCnt, g_cnt);
    cudaGetSymbolAddress(&pPool, g_pool);
    cudaGetSymbolAddress(&pAlloc, g_alloc);
    float* bufA = (float*)pA;    // padded (64)
    float* bufB = (float*)pB;    // padded (96)
    float* t1   = (float*)pT1;   // padded (64)
    float* t2   = (float*)pT2;   // padded (64)

    const int AGG_GRID  = (NN + 3) / 4;
    const int GEMM_GRID = (NN + 255) / 256;

    cudaMemsetAsync(pCnt, 0, NN * sizeof(int));
    cudaMemsetAsync(pPool, 0, GG * FDIM * sizeof(unsigned));
    cudaMemsetAsync(pAlloc, 0, sizeof(int));

    // CSR build
    hist_k<<<(EE + 255) / 256, 256>>>(dst);                          // 1
    alloc_k<<<(NN + 255) / 256, 256>>>();                            // 2
    bin_k<<<(EE + 255) / 256, 256>>>(src, dst);                      // 3

    // layer 1 (transform-first): t1 = x@W1 (padded) ; bufA = relu(agg(t1)+b1)
    gemm4_k<44, 44, 44, PAD, false><<<dim3(GEMM_GRID, 2), 256>>>(x, W1, nullptr, t1);  // 4 (profiled)
    agg44_k<1><<<AGG_GRID, 128>>>(t1, b1, bufA, nullptr);            // 5

    // layer 2 (aggregate-first): t2 = agg(bufA) ; bufB = relu(t2@W2+b2) (96-pad)
    agg44_k<0><<<AGG_GRID, 128>>>(bufA, nullptr, t2, nullptr);       // 6
    gemm4_k<44, PAD, 88, 96, true><<<dim3(GEMM_GRID, 4), 256>>>(t2, W2, b2, bufB);     // 7

    // layer 3 (transform-first): t1 = bufB@W3 ; pool(relu(agg(t1)+b3))
    gemm4_k<88, 96, 44, PAD, false><<<dim3(GEMM_GRID, 2), 256>>>(bufB, W3, nullptr, t1); // 8
    agg44_k<2><<<AGG_GRID, 128>>>(t1, b3, nullptr, batch);           // 9

    // heads
    final_k<<<GG / 8, 256>>>(feature, Wg, bg, Wf1, bf1, Wf2, bf2, out);  // 10
}

// round 16
// speedup vs baseline: 1.0593x; 1.0593x over previous
#include <cuda_runtime.h>

#define NN 100000
#define EE 1000000
#define GG 1024
#define FDIM 44
#define FEATD 1019
#define GCOLS 22
#define GCP   24   // padded sW row (6 x ulonglong2)

// ---------------- static scratch ----------------
__device__ int      g_cnt[NN];
__device__ int      g_off[NN];
__device__ int      g_cur[NN];
__device__ int      g_alloc;
__device__ float    g_dinv[NN];
__device__ __align__(16) float2 g_csr[EE + NN];  // {src*44 (int bits), norm}; rows even-aligned
__device__ __align__(16) float g_bufA[(size_t)NN * FDIM];
__device__ __align__(16) float g_bufB[(size_t)NN * 2 * FDIM];
__device__ __align__(16) float g_t1[(size_t)NN * FDIM];
__device__ __align__(16) float g_t2[(size_t)NN * FDIM];
__device__ unsigned g_pool[GG * FDIM];

// ---------------- histogram ----------------
__global__ void hist_k(const int* __restrict__ dst) {
    int e = blockIdx.x * blockDim.x + threadIdx.x;
    if (e < EE) atomicAdd(&g_cnt[dst[e]], 1);
}

// ---------------- bump allocation of CSR rows (even-aligned starts) ----------
__global__ void alloc_k() {
    int i = blockIdx.x * blockDim.x + threadIdx.x;
    int lane = threadIdx.x & 31;
    int c = (i < NN) ? g_cnt[i] : 0;
    int cp = (c + 1) & ~1;
    int s = cp;
#pragma unroll
    for (int o = 1; o < 32; o <<= 1) {
        int t = __shfl_up_sync(0xffffffffu, s, o);
        if (lane >= o) s += t;
    }
    int base = 0;
    if (lane == 31) base = atomicAdd(&g_alloc, s);
    base = __shfl_sync(0xffffffffu, base, 31);
    int off = base + s - cp;
    if (i < NN) {
        g_off[i] = off;
        g_cur[i] = off;
        g_dinv[i] = rsqrtf((float)c + 1.0f);
    }
}

// ---------------- edge binning (store pre-scaled float offset src*44) --------
__global__ void bin_k(const int* __restrict__ src, const int* __restrict__ dst) {
    int e = blockIdx.x * blockDim.x + threadIdx.x;
    if (e >= EE) return;
    int s = __ldg(&src[e]);
    int d = __ldg(&dst[e]);
    int pos = atomicAdd(&g_cur[d], 1);
    g_csr[pos] = make_float2(__int_as_float(s * FDIM), g_dinv[s] * g_dinv[d]);
}

// ---------------- warp-per-node aggregation (two chunks: lane, 32+lane) ------
// MODE 0: plain   MODE 1: relu(agg + b)   MODE 2: pool(relu(agg + b))
template <int MODE>
__global__ __launch_bounds__(128) void agg44_k(const float* __restrict__ in,
                                               const float* __restrict__ b,
                                               float* __restrict__ out,
                                               const int* __restrict__ batch) {
    int node = blockIdx.x * 4 + (threadIdx.x >> 5);
    if (node >= NN) return;
    const int lane = threadIdx.x & 31;
    const bool hi = lane < (FDIM - 32);   // 12 lanes own chunk 1

    const float* __restrict__ base0 = in + lane;
    const int selfoff = node * FDIM;

    float di = g_dinv[node];
    float sc = di * di;
    float acc0 = __ldg(&base0[selfoff]) * sc;
    float acc1 = hi ? __ldg(&base0[selfoff + 32]) * sc : 0.0f;

    const int n = g_cnt[node];
    const float2* __restrict__ csr = g_csr + g_off[node];   // even-aligned

    int j = 0;
    for (; j + 4 <= n; j += 4) {
        const float4* c4 = reinterpret_cast<const float4*>(csr + j);
        float4 p0 = __ldg(&c4[0]);
        float4 p1 = __ldg(&c4[1]);
        int o0 = __float_as_int(p0.x), o1 = __float_as_int(p0.z);
        int o2 = __float_as_int(p1.x), o3 = __float_as_int(p1.z);
        float v00 = __ldg(&base0[o0]);
        float v10 = __ldg(&base0[o1]);
        float v20 = __ldg(&base0[o2]);
        float v30 = __ldg(&base0[o3]);
        float v01 = hi ? __ldg(&base0[o0 + 32]) : 0.0f;
        float v11 = hi ? __ldg(&base0[o1 + 32]) : 0.0f;
        float v21 = hi ? __ldg(&base0[o2 + 32]) : 0.0f;
        float v31 = hi ? __ldg(&base0[o3 + 32]) : 0.0f;
        acc0 += v00 * p0.y + v10 * p0.w + v20 * p1.y + v30 * p1.w;
        acc1 += v01 * p0.y + v11 * p0.w + v21 * p1.y + v31 * p1.w;
    }
    for (; j < n; j++) {
        float2 c = __ldg(&csr[j]);
        int o = __float_as_int(c.x);
        acc0 += __ldg(&base0[o]) * c.y;
        if (hi) acc1 += __ldg(&base0[o + 32]) * c.y;
    }

    if (MODE == 2) {
        acc0 = fmaxf(acc0 + __ldg(&b[lane]), 0.0f);
        unsigned gbase = (unsigned)__ldg(&batch[node]) * FDIM;
        atomicMax(&g_pool[gbase + lane], __float_as_uint(acc0));
        if (hi) {
            acc1 = fmaxf(acc1 + __ldg(&b[32 + lane]), 0.0f);
            atomicMax(&g_pool[gbase + 32 + lane], __float_as_uint(acc1));
        }
    } else {
        if (MODE == 1) {
            acc0 = fmaxf(acc0 + __ldg(&b[lane]), 0.0f);
            if (hi) acc1 = fmaxf(acc1 + __ldg(&b[32 + lane]), 0.0f);
        }
        out[selfoff + lane] = acc0;
        if (hi) out[selfoff + 32 + lane] = acc1;
    }
}

// ---------------- GEMM v4: smem-staged, fully coalesced global I/O -----------
template <int FIN, int INS, int FOUT, int OUTS, bool RELU>
__global__ __launch_bounds__(256, 4) void gemm4_k(const float* __restrict__ in,
                                                  const float* __restrict__ W,
                                                  const float* __restrict__ b,
                                                  float* __restrict__ out) {
    constexpr int NPHASE = FIN / 44;
    __shared__ __align__(16) float sIn[256 * 44];   // 45KB; reused as output staging
    __shared__ __align__(16) float sW[FIN * GCP];
    __shared__ float sB[GCOLS];

    const int t = threadIdx.x;
    const int col0 = blockIdx.y * GCOLS;
    const int n0 = blockIdx.x * 256;
    const int nrows = (NN - n0 < 256) ? (NN - n0) : 256;

    for (int i = t; i < FIN * GCP; i += 256) {
        int k = i / GCP, c = i - k * GCP;
        sW[i] = (c < GCOLS) ? W[k * FOUT + col0 + c] : 0.0f;
    }
    if (t < GCOLS) sB[t] = b ? b[col0 + t] : 0.0f;

    unsigned long long acc[11];

    const float4* __restrict__ gin = reinterpret_cast<const float4*>(in);
#pragma unroll 1
    for (int p = 0; p < NPHASE; p++) {
        __syncthreads();
#pragma unroll
        for (int s = 0; s < 11; s++) {
            int i = t + 256 * s;
            int row = i / 11;
            int c = i - row * 11;
            float4 v = (row < nrows)
                ? __ldg(&gin[(size_t)(n0 + row) * (INS / 4) + p * 11 + c])
                : make_float4(0.f, 0.f, 0.f, 0.f);
            reinterpret_cast<float4*>(sIn)[i] = v;
        }
        __syncthreads();
        if (p == 0) {
#pragma unroll
            for (int c2 = 0; c2 < 11; c2++) {
                float lo = sB[2 * c2], hi = sB[2 * c2 + 1];
                asm("mov.b64 %0, {%1, %2};" : "=l"(acc[c2]) : "f"(lo), "f"(hi));
            }
        }
        const float4* __restrict__ s4 = reinterpret_cast<const float4*>(sIn) + t * 11;
#pragma unroll
        for (int k4 = 0; k4 < 11; k4++) {
            float4 a = s4[k4];
            float av[4] = {a.x, a.y, a.z, a.w};
#pragma unroll
            for (int kk = 0; kk < 4; kk++) {
                const int k = p * 44 + k4 * 4 + kk;
                unsigned long long ad;
                asm("mov.b64 %0, {%1, %1};" : "=l"(ad) : "f"(av[kk]));
                const ulonglong2* __restrict__ w2p =
                    reinterpret_cast<const ulonglong2*>(sW + k * GCP);
#pragma unroll
                for (int c2 = 0; c2 < 6; c2++) {
                    ulonglong2 wv = w2p[c2];
                    asm("fma.rn.f32x2 %0, %1, %2, %0;" : "+l"(acc[2 * c2 > 10 ? 10 : 2 * c2]) : "l"(ad), "l"(wv.x));
                    if (2 * c2 + 1 < 11) {
                        asm("fma.rn.f32x2 %0, %1, %2, %0;" : "+l"(acc[2 * c2 + 1]) : "l"(ad), "l"(wv.y));
                    }
                }
            }
        }
    }
    __syncthreads();

    unsigned long long* so = reinterpret_cast<unsigned long long*>(sIn);
#pragma unroll
    for (int c2 = 0; c2 < 11; c2++) {
        float lo, hi;
        asm("mov.b64 {%0, %1}, %2;" : "=f"(lo), "=f"(hi) : "l"(acc[c2]));
        if (RELU) { lo = fmaxf(lo, 0.0f); hi = fmaxf(hi, 0.0f); }
        unsigned long long v;
        asm("mov.b64 %0, {%1, %2};" : "=l"(v) : "f"(lo), "f"(hi));
        so[t * 11 + c2] = v;
    }
    __syncthreads();

    float2* __restrict__ gout = reinterpret_cast<float2*>(out);
#pragma unroll
    for (int s = 0; s < 11; s++) {
        int i = t + 256 * s;
        int row = i / 11;
        int c = i - row * 11;
        if (row < nrows)
            gout[(size_t)(n0 + row) * (OUTS / 2) + col0 / 2 + c] =
                reinterpret_cast<float2*>(sIn)[i];
    }
}

// ---------------- heads (split-K over 2 thread halves) ----------------
__global__ __launch_bounds__(256) void final_k(
        const float* __restrict__ feature,
        const float* __restrict__ Wg,  const float* __restrict__ bg,
        const float* __restrict__ Wf1, const float* __restrict__ bf1,
        const float* __restrict__ Wf2, const float* __restrict__ bf2,
        float* __restrict__ out) {
    constexpr int GPB = 8;
    constexpr int KSPLIT = 512;
    __shared__ float sf[GPB][1024];
    __shared__ float sacc[GPB][128];
    __shared__ float red1[GPB][4], red2[GPB][4];
    const int g0 = blockIdx.x * GPB;
    const int t = threadIdx.x;   // 256
    const int h = t & 127;
    const int half = t >> 7;

#pragma unroll
    for (int q = 0; q < GPB; q++)
        for (int k = t; k < FEATD; k += 256)
            sf[q][k] = feature[(size_t)(g0 + q) * FEATD + k];
    __syncthreads();

    float acc[GPB];
    const float bb = (half == 0) ? bf1[h] : 0.0f;
#pragma unroll
    for (int q = 0; q < GPB; q++) acc[q] = bb;
    const int k0 = half ? KSPLIT : 0;
    const int k1 = half ? FEATD : KSPLIT;
    for (int k = k0; k < k1; k++) {
        float w = __ldg(&Wf1[k * 128 + h]);
#pragma unroll
        for (int q = 0; q < GPB; q++) acc[q] += sf[q][k] * w;
    }
    if (half == 1) {
#pragma unroll
        for (int q = 0; q < GPB; q++) sacc[q][h] = acc[q];
    }
    __syncthreads();

    if (half == 0) {
        const float w2 = Wf2[h];
        const float wg = (h < FDIM) ? Wg[h] : 0.0f;
        const int lane = h & 31, wid = h >> 5;
#pragma unroll
        for (int q = 0; q < GPB; q++) {
            float hidden = acc[q] + sacc[q][h];
            float s2 = fmaxf(hidden, 0.0f) * w2;
            float s1 = (h < FDIM) ? __uint_as_float(g_pool[(g0 + q) * FDIM + h]) * wg : 0.0f;
#pragma unroll
            for (int o = 16; o; o >>= 1) {
                s1 += __shfl_down_sync(0xffffffffu, s1, o);
                s2 += __shfl_down_sync(0xffffffffu, s2, o);
            }
            if (lane == 0) { red1[q][wid] = s1; red2[q][wid] = s2; }
        }
    }
    __syncthreads();
    if (t < GPB) {
        int q = t;
        float a = red1[q][0] + red1[q][1] + red1[q][2] + red1[q][3];
        float c = red2[q][0] + red2[q][1] + red2[q][2] + red2[q][3];
        out[g0 + q] = fmaxf(a + bg[0], 0.0f) + c + bf2[0];
    }
}

// ---------------- launch ----------------
extern "C" void kernel_launch(void* const* d_in, const int* in_sizes, int n_in,
                              void* d_out, int out_size) {
    const float* x       = (const float*)d_in[0];
    const int*   ei      = (const int*)d_in[1];
    const int*   batch   = (const int*)d_in[2];
    const float* feature = (const float*)d_in[3];
    const float* W1 = (const float*)d_in[4];
    const float* b1 = (const float*)d_in[5];
    const float* W2 = (const float*)d_in[6];
    const float* b2 = (const float*)d_in[7];
    const float* W3 = (const float*)d_in[8];
    const float* b3 = (const float*)d_in[9];
    const float* Wg = (const float*)d_in[10];
    const float* bg = (const float*)d_in[11];
    const float* Wf1 = (const float*)d_in[12];
    const float* bf1 = (const float*)d_in[13];
    const float* Wf2 = (const float*)d_in[14];
    const float* bf2 = (const float*)d_in[15];
    float* out = (float*)d_out;

    const int* src = ei;        // edge_index[0]
    const int* dst = ei + EE;   // edge_index[1]

    void *pA, *pB, *pT1, *pT2, *pCnt, *pPool, *pAlloc;
    cudaGetSymbolAddress(&pA, g_bufA);
    cudaGetSymbolAddress(&pB, g_bufB);
    cudaGetSymbolAddress(&pT1, g_t1);
    cudaGetSymbolAddress(&pT2, g_t2);
    cudaGetSymbolAddress(&pCnt, g_cnt);
    cudaGetSymbolAddress(&pPool, g_pool);
    cudaGetSymbolAddress(&pAlloc, g_alloc);
    float* bufA = (float*)pA;
    float* bufB = (float*)pB;
    float* t1   = (float*)pT1;
    float* t2   = (float*)pT2;

    const int AGG_GRID  = (NN + 3) / 4;
    const int GEMM_GRID = (NN + 255) / 256;

    cudaMemsetAsync(pCnt, 0, NN * sizeof(int));
    cudaMemsetAsync(pPool, 0, GG * FDIM * sizeof(unsigned));
    cudaMemsetAsync(pAlloc, 0, sizeof(int));

    // CSR build
    hist_k<<<(EE + 255) / 256, 256>>>(dst);                          // 1
    alloc_k<<<(NN + 255) / 256, 256>>>();                            // 2
    bin_k<<<(EE + 255) / 256, 256>>>(src, dst);                      // 3

    // layer 1 (transform-first): t1 = x@W1 (x streamed, DRAM-efficient);
    //                            bufA = relu(agg(t1)+b1) (t1 gathered from L2)
    gemm4_k<44, 44, 44, 44, false><<<dim3(GEMM_GRID, 2), 256>>>(x, W1, nullptr, t1);  // 4 (profiled)
    agg44_k<1><<<AGG_GRID, 128>>>(t1, b1, bufA, nullptr);            // 5

    // layer 2 (aggregate-first): t2 = agg(bufA) ; bufB = relu(t2@W2+b2)
    agg44_k<0><<<AGG_GRID, 128>>>(bufA, nullptr, t2, nullptr);       // 6
    gemm4_k<44, 44, 88, 88, true><<<dim3(GEMM_GRID, 4), 256>>>(t2, W2, b2, bufB);     // 7

    // layer 3 (transform-first): t1 = bufB@W3 ; pool(relu(agg(t1)+b3))
    gemm4_k<88, 88, 44, 44, false><<<dim3(GEMM_GRID, 2), 256>>>(bufB, W3, nullptr, t1); // 8
    agg44_k<2><<<AGG_GRID, 128>>>(t1, b3, nullptr, batch);           // 9

    // heads
    final_k<<<GG / 8, 256>>>(feature, Wg, bg, Wf1, bf1, Wf2, bf2, out);  // 10
}